// round 9
// baseline (speedup 1.0000x reference)
#include <cuda_runtime.h>
#include <cstdint>

#define SEQ 2048
#define HD 64
#define NBH 32
#define TOPK 32
#define FW 8            // warps per finalize block
#define LCAP 128
#define CCAP 512

typedef unsigned long long u64;

__device__ __forceinline__ u64 dup2(float x) {
    u64 r; asm("mov.b64 %0, {%1, %1};" : "=l"(r) : "f"(x)); return r;
}
__device__ __forceinline__ void fma2(u64& c, u64 a, u64 b) {
    asm("fma.rn.f32x2 %0, %1, %2, %0;" : "+l"(c) : "l"(a), "l"(b));
}
__device__ __forceinline__ unsigned fkey(float f) {
    unsigned u = __float_as_uint(f);
    return (u & 0x80000000u) ? ~u : (u | 0x80000000u);
}
__device__ __forceinline__ float unfkey(unsigned k) {
    return (k & 0x80000000u) ? __uint_as_float(k & 0x7FFFFFFFu) : __uint_as_float(~k);
}

// ---------------------------------------------------------------------------
// Kernel 1 (R5 GEMM, measured 575us): scores = (q/8).k via packed f32x2 FMA.
// 128(i) x 64(j) tile, 128 threads, 8x8 microtile. Epilogue stores scores as
// order-preserving radix KEYS (fkey) and prefills mask = 1.0f.
// ---------------------------------------------------------------------------
__global__ __launch_bounds__(128) void score_kernel(
    const float* __restrict__ q, const float* __restrict__ k,
    unsigned* __restrict__ keys, float* __restrict__ maskp)
{
    __shared__ float QsT[HD * 128];   // [d][i], 32 KB
    __shared__ float KsT[HD * 64];    // [d][j], 16 KB

    const int t = threadIdx.x;
    const int bh = blockIdx.z;
    const float* qb = q + ((size_t)bh * SEQ + blockIdx.y * 128) * HD;
    const float* kb = k + ((size_t)bh * SEQ + blockIdx.x * 64) * HD;

#pragma unroll
    for (int it = 0; it < 16; it++) {
        int idx = t + 128 * it;
        int d4 = idx >> 7, row = idx & 127;
        float4 val = *(const float4*)(qb + row * HD + d4 * 4);
        QsT[(d4 * 4 + 0) * 128 + row] = val.x * 0.125f;
        QsT[(d4 * 4 + 1) * 128 + row] = val.y * 0.125f;
        QsT[(d4 * 4 + 2) * 128 + row] = val.z * 0.125f;
        QsT[(d4 * 4 + 3) * 128 + row] = val.w * 0.125f;
    }
#pragma unroll
    for (int it = 0; it < 8; it++) {
        int idx = t + 128 * it;
        int d4 = idx >> 6, row = idx & 63;
        float4 val = *(const float4*)(kb + row * HD + d4 * 4);
        KsT[(d4 * 4 + 0) * 64 + row] = val.x;
        KsT[(d4 * 4 + 1) * 64 + row] = val.y;
        KsT[(d4 * 4 + 2) * 64 + row] = val.z;
        KsT[(d4 * 4 + 3) * 64 + row] = val.w;
    }
    __syncthreads();

    const int ti = t >> 3, tj = t & 7;
    u64 acc[8][4];
#pragma unroll
    for (int i = 0; i < 8; i++)
#pragma unroll
        for (int p = 0; p < 4; p++) acc[i][p] = 0ull;

    const float4* Q4 = (const float4*)QsT;
    const u64* K2 = (const u64*)KsT;

#pragma unroll 8
    for (int d = 0; d < HD; d++) {
        float4 a0 = Q4[d * 32 + ti * 2];
        float4 a1 = Q4[d * 32 + ti * 2 + 1];
        u64 b0 = K2[d * 32 + tj * 4 + 0];
        u64 b1 = K2[d * 32 + tj * 4 + 1];
        u64 b2 = K2[d * 32 + tj * 4 + 2];
        u64 b3 = K2[d * 32 + tj * 4 + 3];
        float av[8] = {a0.x, a0.y, a0.z, a0.w, a1.x, a1.y, a1.z, a1.w};
#pragma unroll
        for (int i = 0; i < 8; i++) {
            u64 ai = dup2(av[i]);
            fma2(acc[i][0], ai, b0);
            fma2(acc[i][1], ai, b1);
            fma2(acc[i][2], ai, b2);
            fma2(acc[i][3], ai, b3);
        }
    }

    const size_t obase = ((size_t)bh * SEQ + blockIdx.y * 128 + ti * 8) * SEQ
                       + blockIdx.x * 64 + tj * 8;
#pragma unroll
    for (int i = 0; i < 8; i++) {
        float2 f0 = *(float2*)&acc[i][0];
        float2 f1 = *(float2*)&acc[i][1];
        float2 f2 = *(float2*)&acc[i][2];
        float2 f3 = *(float2*)&acc[i][3];
        uint4* o = (uint4*)(keys + obase + (size_t)i * SEQ);
        o[0] = make_uint4(fkey(f0.x), fkey(f0.y), fkey(f1.x), fkey(f1.y));
        o[1] = make_uint4(fkey(f2.x), fkey(f2.y), fkey(f3.x), fkey(f3.y));
    }
    if (maskp) {
        const float4 one4 = make_float4(1.f, 1.f, 1.f, 1.f);
#pragma unroll
        for (int i = 0; i < 8; i++) {
            float4* mo = (float4*)(maskp + obase + (size_t)i * SEQ);
            mo[0] = one4; mo[1] = one4;
        }
    }
}

// ---------------------------------------------------------------------------
// Kernel 2: warp-per-row, 8 warps/block, no row staging (L2-hot re-reads).
// Match-aggregated histogram atomics; candidate VALUES cached in smem;
// fill+keep-compaction merged; kept keys saved so exp needs no re-read.
// ---------------------------------------------------------------------------
__global__ __launch_bounds__(FW * 32) void finalize_kernel(
    const float* __restrict__ v, const unsigned* __restrict__ keysg,
    float* __restrict__ ctx, float* __restrict__ attn, float* __restrict__ maskp)
{
    __shared__ unsigned hist[FW][256];    // 8 KB
    __shared__ unsigned candk[FW][CCAP];  // 16 KB (candidate key values)
    __shared__ int      list[FW][LCAP];   // 4 KB
    __shared__ unsigned klist[FW][LCAP];  // 4 KB (kept key values)
    __shared__ float    plist[FW][LCAP];  // 4 KB

    const int w = threadIdx.x >> 5;
    const int lane = threadIdx.x & 31;
    const size_t R = (size_t)blockIdx.x * FW + w;
    const int bh = (int)(R >> 11);
    const uint4* g4 = (const uint4*)(keysg + R * SEQ);

    // ---- Pass A: row max + aggregated top-byte histogram ----
#pragma unroll
    for (int e = 0; e < 8; e++) hist[w][lane + 32 * e] = 0;
    __syncwarp();
    unsigned mk = 0;
#define HADD(val) { unsigned _b = (val) >> 24;                                  \
        unsigned _mm = __match_any_sync(0xffffffffu, _b);                       \
        if ((unsigned)(__ffs(_mm) - 1) == (unsigned)lane)                       \
            atomicAdd(&hist[w][_b], __popc(_mm)); }
#pragma unroll 4
    for (int it = 0; it < 16; it++) {
        uint4 kv = __ldg(&g4[lane + 32 * it]);
        mk = umax(mk, umax(umax(kv.x, kv.y), umax(kv.z, kv.w)));
        HADD(kv.x); HADD(kv.y); HADD(kv.z); HADD(kv.w);
    }
#pragma unroll
    for (int off = 16; off >= 1; off >>= 1)
        mk = umax(mk, __shfl_xor_sync(0xffffffffu, mk, off));
    const float m = unfkey(mk);
    __syncwarp();

    // ---- Round 1: top byte containing the 32nd-largest ----
    unsigned prefix, prefmask, kk = TOPK, b1;
    {
        unsigned p = 0;
#pragma unroll
        for (int b = 0; b < 8; b++) p += hist[w][lane * 8 + b];
        unsigned S = p;
#pragma unroll
        for (int off = 1; off < 32; off <<= 1) {
            unsigned tv = __shfl_down_sync(0xffffffffu, S, off);
            if (lane + off < 32) S += tv;
        }
        unsigned sufExcl = S - p;
        bool mine = (S >= kk) && (sufExcl < kk);
        unsigned bal = __ballot_sync(0xffffffffu, mine);
        int src = __ffs(bal) - 1;
        unsigned chosen = 0, newk = 0;
        if (mine) {
            unsigned cum = sufExcl;
#pragma unroll
            for (int b = 7; b >= 0; b--) {
                unsigned h = hist[w][lane * 8 + b];
                if (cum + h >= kk) { chosen = lane * 8 + b; newk = kk - cum; break; }
                cum += h;
            }
        }
        b1 = __shfl_sync(0xffffffffu, chosen, src);
        kk = __shfl_sync(0xffffffffu, newk, src);
        prefix = b1 << 24;
        prefmask = 0xFF000000u;
    }
    __syncwarp();

    // ---- Pass B: compact candidate VALUES (top byte == b1) ----
    int cbase = 0;
    for (int it = 0; it < 16; it++) {
        uint4 kv = __ldg(&g4[lane + 32 * it]);
        unsigned vals[4] = {kv.x, kv.y, kv.z, kv.w};
#pragma unroll
        for (int cc = 0; cc < 4; cc++) {
            bool isc = (vals[cc] >> 24) == b1;
            unsigned bal = __ballot_sync(0xffffffffu, isc);
            if (isc) {
                int pos = cbase + __popc(bal & ((1u << lane) - 1u));
                if (pos < CCAP) candk[w][pos] = vals[cc];
            }
            cbase += __popc(bal);
        }
    }
    __syncwarp();
    const bool useCand = (cbase <= CCAP);
    const int c = cbase < CCAP ? cbase : CCAP;

    // ---- Rounds 2-4 ----
#pragma unroll
    for (int shift = 16; shift >= 0; shift -= 8) {
#pragma unroll
        for (int e = 0; e < 8; e++) hist[w][lane + 32 * e] = 0;
        __syncwarp();
        if (useCand) {
            int iters = (c + 31) >> 5;
            for (int q2 = 0; q2 < iters; q2++) {
                int e = q2 * 32 + lane;
                bool valid = e < c;
                unsigned u = valid ? candk[w][e] : 0xFFFFFFFFu;
                bool act = valid && ((u & prefmask) == prefix);
                unsigned bin = act ? ((u >> shift) & 255u) : (0x100u + lane);
                unsigned mm = __match_any_sync(0xffffffffu, bin);
                if (act && (unsigned)(__ffs(mm) - 1) == (unsigned)lane)
                    atomicAdd(&hist[w][bin], __popc(mm));
            }
        } else {
            for (int it = 0; it < 16; it++) {
                uint4 kv = __ldg(&g4[lane + 32 * it]);
                unsigned vals[4] = {kv.x, kv.y, kv.z, kv.w};
#pragma unroll
                for (int cc = 0; cc < 4; cc++) {
                    unsigned u = vals[cc];
                    bool act = (u & prefmask) == prefix;
                    unsigned bin = act ? ((u >> shift) & 255u) : (0x100u + lane);
                    unsigned mm = __match_any_sync(0xffffffffu, bin);
                    if (act && (unsigned)(__ffs(mm) - 1) == (unsigned)lane)
                        atomicAdd(&hist[w][bin], __popc(mm));
                }
            }
        }
        __syncwarp();
        unsigned p = 0;
#pragma unroll
        for (int b = 0; b < 8; b++) p += hist[w][lane * 8 + b];
        unsigned S = p;
#pragma unroll
        for (int off = 1; off < 32; off <<= 1) {
            unsigned tv = __shfl_down_sync(0xffffffffu, S, off);
            if (lane + off < 32) S += tv;
        }
        unsigned sufExcl = S - p;
        bool mine = (S >= kk) && (sufExcl < kk);
        unsigned bal = __ballot_sync(0xffffffffu, mine);
        int src = __ffs(bal) - 1;
        unsigned chosen = 0, newk = 0;
        if (mine) {
            unsigned cum = sufExcl;
#pragma unroll
            for (int b = 7; b >= 0; b--) {
                unsigned h = hist[w][lane * 8 + b];
                if (cum + h >= kk) { chosen = lane * 8 + b; newk = kk - cum; break; }
                cum += h;
            }
        }
        chosen = __shfl_sync(0xffffffffu, chosen, src);
        kk = __shfl_sync(0xffffffffu, newk, src);
        prefix |= chosen << shift;
        prefmask |= 0xFFu << shift;
        __syncwarp();
    }
    const unsigned tkey = prefix;   // exact key of the 32nd-largest

    // ---- Pass C: keep-compaction (saving keys) fused with attn=0 fill ----
    float4* a4 = (float4*)(attn + R * SEQ);
    const float4 z4 = make_float4(0.f, 0.f, 0.f, 0.f);
    int base = 0;
    for (int it = 0; it < 16; it++) {
        int e4 = lane + 32 * it;
        uint4 kv = __ldg(&g4[e4]);
        unsigned vals[4] = {kv.x, kv.y, kv.z, kv.w};
#pragma unroll
        for (int cc = 0; cc < 4; cc++) {
            bool keep = vals[cc] >= tkey;
            unsigned bal = __ballot_sync(0xffffffffu, keep);
            if (keep) {
                int pos = base + __popc(bal & ((1u << lane) - 1u));
                if (pos < LCAP) { list[w][pos] = e4 * 4 + cc; klist[w][pos] = vals[cc]; }
            }
            base += __popc(bal);
        }
        a4[e4] = z4;    // overwrite keys with attn zeros (read-before-write per thread)
    }
    __syncwarp();
    const int n = base < LCAP ? base : LCAP;

    // ---- exp on kept; deterministic partition sum ----
    float lsum = 0.f;
    for (int e = lane; e < n; e += 32) {
        float p = __expf(unfkey(klist[w][e]) - m);
        plist[w][e] = p;
        lsum += p;
    }
#pragma unroll
    for (int off = 16; off >= 1; off >>= 1)
        lsum += __shfl_xor_sync(0xffffffffu, lsum, off);
    const float inv = 1.0f / lsum;
    __syncwarp();

    // ---- Scatter kept attn / mask=0; gather-accumulate context ----
    const float* vb = v + (size_t)bh * SEQ * HD;
    float acc0 = 0.f, acc1 = 0.f;
    float* arow = attn + R * SEQ;
    float* mrow = maskp ? maskp + R * SEQ : (float*)0;
    for (int e = 0; e < n; e++) {
        int j = list[w][e];
        float wgt = plist[w][e] * inv;
        if (lane == 0) {
            arow[j] = wgt;
            if (mrow) mrow[j] = 0.f;
        }
        acc0 += wgt * vb[j * HD + lane];
        acc1 += wgt * vb[j * HD + lane + 32];
    }
    if (ctx) {
        ctx[R * HD + lane] = acc0;
        ctx[R * HD + lane + 32] = acc1;
    }
}

// ---------------------------------------------------------------------------
extern "C" void kernel_launch(void* const* d_in, const int* in_sizes, int n_in,
                              void* d_out, int out_size)
{
    if (n_in < 3 || !d_out) return;
    const float* q = (const float*)d_in[0];
    const float* k = (const float*)d_in[1];
    const float* v = (const float*)d_in[2];
    float* out = (float*)d_out;

    const size_t nctx = (size_t)NBH * SEQ * HD;        //   4,194,304
    const size_t nattn = (size_t)NBH * SEQ * SEQ;      // 134,217,728
    float* ctx = 0; float* attn = 0; float* maskp = 0;
    const size_t osz = (size_t)out_size;
    if (osz >= nctx + 2 * nattn) {
        ctx = out; attn = out + nctx; maskp = out + nctx + nattn;
    } else if (osz >= nctx + nattn) {
        ctx = out; attn = out + nctx;
    } else {
        attn = out;
    }

    // Kernel 1 stages score KEYS in the attn segment and prefills mask = 1.
    score_kernel<<<dim3(SEQ / 64, SEQ / 128, NBH), 128>>>(
        q, k, (unsigned*)attn, maskp);
    finalize_kernel<<<(NBH * SEQ) / FW, FW * 32>>>(
        v, (const unsigned*)attn, ctx, attn, maskp);
}

// round 10
// speedup vs baseline: 1.3909x; 1.3909x over previous
#include <cuda_runtime.h>
#include <cstdint>

#define SEQ 2048
#define HD 64
#define NBH 32
#define TOPK 32
#define WPB 4
#define LCAP 128
#define CAND_CAP 512
#define NROWS (NBH * SEQ)

typedef unsigned long long u64;

__device__ __forceinline__ u64 dup2(float x) {
    u64 r; asm("mov.b64 %0, {%1, %1};" : "=l"(r) : "f"(x)); return r;
}
__device__ __forceinline__ void fma2(u64& c, u64 a, u64 b) {
    asm("fma.rn.f32x2 %0, %1, %2, %0;" : "+l"(c) : "l"(a), "l"(b));
}
__device__ __forceinline__ unsigned fkey(float f) {
    unsigned u = __float_as_uint(f);
    return (u & 0x80000000u) ? ~u : (u | 0x80000000u);
}
__device__ __forceinline__ float unfkey(unsigned k) {
    return (k & 0x80000000u) ? __uint_as_float(k & 0x7FFFFFFFu) : __uint_as_float(~k);
}

// ---------------------------------------------------------------------------
// Kernel 1 (R5, measured 575us): scores = (q/8).k via packed f32x2 FMA.
// 128(i) x 64(j) tile, 128 threads, 8x8 microtile. Prefills mask=1 with
// streaming stores (keep L2 for the score lines kernel 2 will read).
// ---------------------------------------------------------------------------
__global__ __launch_bounds__(128) void score_kernel(
    const float* __restrict__ q, const float* __restrict__ k,
    float* __restrict__ scores, float* __restrict__ maskp)
{
    __shared__ float QsT[HD * 128];   // [d][i], 32 KB
    __shared__ float KsT[HD * 64];    // [d][j], 16 KB

    const int t = threadIdx.x;
    const int bh = blockIdx.z;
    const float* qb = q + ((size_t)bh * SEQ + blockIdx.y * 128) * HD;
    const float* kb = k + ((size_t)bh * SEQ + blockIdx.x * 64) * HD;

#pragma unroll
    for (int it = 0; it < 16; it++) {
        int idx = t + 128 * it;
        int d4 = idx >> 7, row = idx & 127;
        float4 val = *(const float4*)(qb + row * HD + d4 * 4);
        QsT[(d4 * 4 + 0) * 128 + row] = val.x * 0.125f;
        QsT[(d4 * 4 + 1) * 128 + row] = val.y * 0.125f;
        QsT[(d4 * 4 + 2) * 128 + row] = val.z * 0.125f;
        QsT[(d4 * 4 + 3) * 128 + row] = val.w * 0.125f;
    }
#pragma unroll
    for (int it = 0; it < 8; it++) {
        int idx = t + 128 * it;
        int d4 = idx >> 6, row = idx & 63;
        float4 val = *(const float4*)(kb + row * HD + d4 * 4);
        KsT[(d4 * 4 + 0) * 64 + row] = val.x;
        KsT[(d4 * 4 + 1) * 64 + row] = val.y;
        KsT[(d4 * 4 + 2) * 64 + row] = val.z;
        KsT[(d4 * 4 + 3) * 64 + row] = val.w;
    }
    __syncthreads();

    const int ti = t >> 3, tj = t & 7;
    u64 acc[8][4];
#pragma unroll
    for (int i = 0; i < 8; i++)
#pragma unroll
        for (int p = 0; p < 4; p++) acc[i][p] = 0ull;

    const float4* Q4 = (const float4*)QsT;
    const u64* K2 = (const u64*)KsT;

#pragma unroll 8
    for (int d = 0; d < HD; d++) {
        float4 a0 = Q4[d * 32 + ti * 2];
        float4 a1 = Q4[d * 32 + ti * 2 + 1];
        u64 b0 = K2[d * 32 + tj * 4 + 0];
        u64 b1 = K2[d * 32 + tj * 4 + 1];
        u64 b2 = K2[d * 32 + tj * 4 + 2];
        u64 b3 = K2[d * 32 + tj * 4 + 3];
        float av[8] = {a0.x, a0.y, a0.z, a0.w, a1.x, a1.y, a1.z, a1.w};
#pragma unroll
        for (int i = 0; i < 8; i++) {
            u64 ai = dup2(av[i]);
            fma2(acc[i][0], ai, b0);
            fma2(acc[i][1], ai, b1);
            fma2(acc[i][2], ai, b2);
            fma2(acc[i][3], ai, b3);
        }
    }

    const size_t obase = ((size_t)bh * SEQ + blockIdx.y * 128 + ti * 8) * SEQ
                       + blockIdx.x * 64 + tj * 8;
#pragma unroll
    for (int i = 0; i < 8; i++) {
        u64* o = (u64*)(scores + obase + (size_t)i * SEQ);
        o[0] = acc[i][0]; o[1] = acc[i][1]; o[2] = acc[i][2]; o[3] = acc[i][3];
    }
    if (maskp) {
        const float4 one4 = make_float4(1.f, 1.f, 1.f, 1.f);
#pragma unroll
        for (int i = 0; i < 8; i++) {
            float4* mo = (float4*)(maskp + obase + (size_t)i * SEQ);
            __stcs(mo, one4); __stcs(mo + 1, one4);
        }
    }
}

// ---------------------------------------------------------------------------
// Kernel 2 (R5 structure, measured 549us): warp-per-row, smem-staged keys,
// exact radix select, sparse softmax + context. Rows processed in REVERSE
// order so the first reads hit score lines still resident in L2 from kernel 1.
// attn zero-fill uses streaming stores. Dual-accumulator V gather.
// ---------------------------------------------------------------------------
__global__ __launch_bounds__(WPB * 32) void finalize_kernel(
    const float* __restrict__ v, const float* __restrict__ scores,
    float* __restrict__ ctx, float* __restrict__ attn, float* __restrict__ maskp)
{
    __shared__ unsigned srow[WPB][SEQ];
    __shared__ unsigned hist[WPB][256];
    __shared__ unsigned short cand[WPB][CAND_CAP];
    __shared__ int list[WPB][LCAP];
    __shared__ float plist[WPB][LCAP];

    const int w = threadIdx.x >> 5;
    const int lane = threadIdx.x & 31;
    const size_t R = (size_t)(NROWS - 1) - ((size_t)blockIdx.x * WPB + w);
    const int bh = (int)(R >> 11);

    const float4* g4 = (const float4*)(scores + R * SEQ);
    uint4* s4 = (uint4*)srow[w];
    float m = __int_as_float(0xff800000);
#pragma unroll
    for (int it = 0; it < 16; it++) {
        float4 val = g4[lane + 32 * it];
        s4[lane + 32 * it] = make_uint4(fkey(val.x), fkey(val.y), fkey(val.z), fkey(val.w));
        m = fmaxf(m, fmaxf(fmaxf(val.x, val.y), fmaxf(val.z, val.w)));
    }
#pragma unroll
    for (int off = 16; off >= 1; off >>= 1)
        m = fmaxf(m, __shfl_xor_sync(0xffffffffu, m, off));
    __syncwarp();

#pragma unroll
    for (int e = 0; e < 8; e++) hist[w][lane + 32 * e] = 0;
    __syncwarp();
    for (int it = 0; it < 64; it++)
        atomicAdd(&hist[w][srow[w][lane + 32 * it] >> 24], 1u);
    __syncwarp();

    unsigned prefix, prefmask, kk = TOPK;
    unsigned b1;
    {
        unsigned p = 0;
#pragma unroll
        for (int b = 0; b < 8; b++) p += hist[w][lane * 8 + b];
        unsigned S = p;
#pragma unroll
        for (int off = 1; off < 32; off <<= 1) {
            unsigned tv = __shfl_down_sync(0xffffffffu, S, off);
            if (lane + off < 32) S += tv;
        }
        unsigned sufExcl = S - p;
        bool mine = (S >= kk) && (sufExcl < kk);
        unsigned bal = __ballot_sync(0xffffffffu, mine);
        int src = __ffs(bal) - 1;
        unsigned chosen = 0, newk = 0;
        if (mine) {
            unsigned cum = sufExcl;
#pragma unroll
            for (int b = 7; b >= 0; b--) {
                unsigned h = hist[w][lane * 8 + b];
                if (cum + h >= kk) { chosen = lane * 8 + b; newk = kk - cum; break; }
                cum += h;
            }
        }
        b1 = __shfl_sync(0xffffffffu, chosen, src);
        kk = __shfl_sync(0xffffffffu, newk, src);
        prefix = b1 << 24;
        prefmask = 0xFF000000u;
    }
    __syncwarp();

    int cbase = 0;
    for (int it = 0; it < 64; it++) {
        int j = lane + 32 * it;
        bool isc = (srow[w][j] >> 24) == b1;
        unsigned bal = __ballot_sync(0xffffffffu, isc);
        if (isc) {
            int pos = cbase + __popc(bal & ((1u << lane) - 1u));
            if (pos < CAND_CAP) cand[w][pos] = (unsigned short)j;
        }
        cbase += __popc(bal);
    }
    __syncwarp();
    const bool useCand = (cbase <= CAND_CAP);
    const int c = cbase < CAND_CAP ? cbase : CAND_CAP;

#pragma unroll
    for (int shift = 16; shift >= 0; shift -= 8) {
#pragma unroll
        for (int e = 0; e < 8; e++) hist[w][lane + 32 * e] = 0;
        __syncwarp();
        if (useCand) {
            for (int e = lane; e < c; e += 32) {
                unsigned u = srow[w][cand[w][e]];
                if ((u & prefmask) == prefix)
                    atomicAdd(&hist[w][(u >> shift) & 255u], 1u);
            }
        } else {
            for (int it = 0; it < 64; it++) {
                unsigned u = srow[w][lane + 32 * it];
                if ((u & prefmask) == prefix)
                    atomicAdd(&hist[w][(u >> shift) & 255u], 1u);
            }
        }
        __syncwarp();
        unsigned p = 0;
#pragma unroll
        for (int b = 0; b < 8; b++) p += hist[w][lane * 8 + b];
        unsigned S = p;
#pragma unroll
        for (int off = 1; off < 32; off <<= 1) {
            unsigned tv = __shfl_down_sync(0xffffffffu, S, off);
            if (lane + off < 32) S += tv;
        }
        unsigned sufExcl = S - p;
        bool mine = (S >= kk) && (sufExcl < kk);
        unsigned bal = __ballot_sync(0xffffffffu, mine);
        int src = __ffs(bal) - 1;
        unsigned chosen = 0, newk = 0;
        if (mine) {
            unsigned cum = sufExcl;
#pragma unroll
            for (int b = 7; b >= 0; b--) {
                unsigned h = hist[w][lane * 8 + b];
                if (cum + h >= kk) { chosen = lane * 8 + b; newk = kk - cum; break; }
                cum += h;
            }
        }
        chosen = __shfl_sync(0xffffffffu, chosen, src);
        kk = __shfl_sync(0xffffffffu, newk, src);
        prefix |= chosen << shift;
        prefmask |= 0xFFu << shift;
        __syncwarp();
    }
    const unsigned tkey = prefix;

    // attn = 0 streaming fill (evict-first; kept entries scattered below)
    float4* a4 = (float4*)(attn + R * SEQ);
    const float4 zero4 = make_float4(0.f, 0.f, 0.f, 0.f);
#pragma unroll
    for (int it = 0; it < 16; it++) __stcs(&a4[lane + 32 * it], zero4);

    int base = 0;
    for (int it = 0; it < 64; it++) {
        int j = lane + 32 * it;
        bool keep = srow[w][j] >= tkey;
        unsigned bal = __ballot_sync(0xffffffffu, keep);
        if (keep) {
            int pos = base + __popc(bal & ((1u << lane) - 1u));
            if (pos < LCAP) list[w][pos] = j;
        }
        base += __popc(bal);
    }
    __syncwarp();
    const int n = base < LCAP ? base : LCAP;

    float lsum = 0.f;
    for (int e = lane; e < n; e += 32) {
        float s = unfkey(srow[w][list[w][e]]);
        float p = __expf(s - m);
        plist[w][e] = p;
        lsum += p;
    }
#pragma unroll
    for (int off = 16; off >= 1; off >>= 1)
        lsum += __shfl_xor_sync(0xffffffffu, lsum, off);
    const float inv = 1.0f / lsum;
    __syncwarp();

    // Scatter kept attn / mask=0; dual-accumulator V gather (deterministic).
    const float* vb = v + (size_t)bh * SEQ * HD;
    float acc0a = 0.f, acc1a = 0.f, acc0b = 0.f, acc1b = 0.f;
    float* arow = attn + R * SEQ;
    float* mrow = maskp ? maskp + R * SEQ : (float*)0;
    int e = 0;
    for (; e + 1 < n; e += 2) {
        int j0 = list[w][e], j1 = list[w][e + 1];
        float w0 = plist[w][e] * inv, w1 = plist[w][e + 1] * inv;
        float v00 = __ldg(vb + j0 * HD + lane);
        float v01 = __ldg(vb + j0 * HD + lane + 32);
        float v10 = __ldg(vb + j1 * HD + lane);
        float v11 = __ldg(vb + j1 * HD + lane + 32);
        if (lane == 0) {
            arow[j0] = w0; arow[j1] = w1;
            if (mrow) { mrow[j0] = 0.f; mrow[j1] = 0.f; }
        }
        acc0a += w0 * v00; acc1a += w0 * v01;
        acc0b += w1 * v10; acc1b += w1 * v11;
    }
    if (e < n) {
        int j0 = list[w][e];
        float w0 = plist[w][e] * inv;
        if (lane == 0) {
            arow[j0] = w0;
            if (mrow) mrow[j0] = 0.f;
        }
        acc0a += w0 * __ldg(vb + j0 * HD + lane);
        acc1a += w0 * __ldg(vb + j0 * HD + lane + 32);
    }
    if (ctx) {
        ctx[R * HD + lane] = acc0a + acc0b;
        ctx[R * HD + lane + 32] = acc1a + acc1b;
    }
}

// ---------------------------------------------------------------------------
extern "C" void kernel_launch(void* const* d_in, const int* in_sizes, int n_in,
                              void* d_out, int out_size)
{
    if (n_in < 3 || !d_out) return;
    const float* q = (const float*)d_in[0];
    const float* k = (const float*)d_in[1];
    const float* v = (const float*)d_in[2];
    float* out = (float*)d_out;

    const size_t nctx = (size_t)NBH * SEQ * HD;        //   4,194,304
    const size_t nattn = (size_t)NBH * SEQ * SEQ;      // 134,217,728
    float* ctx = 0; float* attn = 0; float* maskp = 0;
    const size_t osz = (size_t)out_size;
    if (osz >= nctx + 2 * nattn) {
        ctx = out; attn = out + nctx; maskp = out + nctx + nattn;
    } else if (osz >= nctx + nattn) {
        ctx = out; attn = out + nctx;
    } else {
        attn = out;
    }

    // Kernel 1 stages raw scores in the attn segment and prefills mask = 1.
    score_kernel<<<dim3(SEQ / 64, SEQ / 128, NBH), 128>>>(q, k, attn, maskp);
    finalize_kernel<<<NROWS / WPB, WPB * 32>>>(v, attn, ctx, attn, maskp);
}